// round 4
// baseline (speedup 1.0000x reference)
#include <cuda_runtime.h>
#include <cuda_bf16.h>
#include <math.h>

#define T_SEQ   512
#define GATES   500
#define HID     125
#define DHID    250      // 2*HID
#define MLPH    512
#define NN      512

// Scratch (device globals; no allocation allowed)
__device__ float g_A[2 * T_SEQ * GATES];   // input projections (fwd/bwd)
__device__ float g_H[T_SEQ * DHID];        // concat hidden states
__device__ float g_P[2 * NN * MLPH];       // Pa, Pb(+b1)

// ---------------------------------------------------------------------------
// helpers
// ---------------------------------------------------------------------------
typedef unsigned long long ull;

__device__ __forceinline__ ull ffma2u(ull a, ull b, ull c) {
    ull d;
    asm("fma.rn.f32x2 %0, %1, %2, %3;" : "=l"(d) : "l"(a), "l"(b), "l"(c));
    return d;
}
__device__ __forceinline__ float2 u2f2(ull v) {
    float2 r;
    asm("mov.b64 {%0, %1}, %2;" : "=f"(r.x), "=f"(r.y) : "l"(v));
    return r;
}
__device__ __forceinline__ float tanh_mufu(float x) {
    float y;
    asm("tanh.approx.f32 %0, %1;" : "=f"(y) : "f"(x));
    return y;
}
__device__ __forceinline__ float sig_mufu(float x) {
    return 0.5f * tanh_mufu(0.5f * x) + 0.5f;
}

// ---------------------------------------------------------------------------
// Input projection, both directions in one launch.
//   A[dir][m][n] = sum_k x[rowA][k] * Wih_dir[n][k] + bih_dir[n] + bhh_dir[n]
//   rowA = dir ? 511-m : m
// grid (16,16,2), block 256. 32x32 tile, K=125.
// ---------------------------------------------------------------------------
__global__ void __launch_bounds__(256) proj_kernel(
    const float* __restrict__ x,
    const float* __restrict__ Wih_f, const float* __restrict__ bih_f,
    const float* __restrict__ bhh_f,
    const float* __restrict__ Wih_b, const float* __restrict__ bih_b,
    const float* __restrict__ bhh_b,
    float* __restrict__ Aout)
{
    const int dir = blockIdx.z;
    const float* __restrict__ W  = dir ? Wih_b : Wih_f;
    const float* __restrict__ bi = dir ? bih_b : bih_f;
    const float* __restrict__ bh = dir ? bhh_b : bhh_f;
    float* __restrict__ C = Aout + dir * (T_SEQ * GATES);

    __shared__ float As[16][34];
    __shared__ float Bs[16][34];

    const int tid = threadIdx.x;
    const int ti = tid & 15;
    const int tn = tid >> 4;
    const int m0 = blockIdx.x * 32;
    const int n0 = blockIdx.y * 32;

    float acc00 = 0.f, acc01 = 0.f, acc10 = 0.f, acc11 = 0.f;

    for (int kc = 0; kc < 125; kc += 16) {
#pragma unroll
        for (int it = 0; it < 2; ++it) {
            int idx = tid + it * 256;
            int mm = idx >> 4, kk = idx & 15;
            int k = kc + kk;
            int m = m0 + mm;
            int ra = dir ? (T_SEQ - 1 - m) : m;
            As[kk][mm] = (k < 125) ? x[(long)ra * 125 + k] : 0.f;
            int n = n0 + mm;
            Bs[kk][mm] = (n < GATES && k < 125) ? W[(long)n * 125 + k] : 0.f;
        }
        __syncthreads();
#pragma unroll
        for (int kk = 0; kk < 16; ++kk) {
            float2 av = *(const float2*)&As[kk][2 * ti];
            float2 bv = *(const float2*)&Bs[kk][2 * tn];
            acc00 = fmaf(av.x, bv.x, acc00);
            acc01 = fmaf(av.x, bv.y, acc01);
            acc10 = fmaf(av.y, bv.x, acc10);
            acc11 = fmaf(av.y, bv.y, acc11);
        }
        __syncthreads();
    }

    int m_ = m0 + 2 * ti;
    int n_ = n0 + 2 * tn;
    float b0 = 0.f, b1v = 0.f;
    if (n_ < GATES)     b0  = bi[n_] + bh[n_];
    if (n_ + 1 < GATES) b1v = bi[n_ + 1] + bh[n_ + 1];
    if (n_ < GATES) {
        C[(long)m_ * GATES + n_]       = acc00 + b0;
        C[(long)(m_ + 1) * GATES + n_] = acc10 + b0;
    }
    if (n_ + 1 < GATES) {
        C[(long)m_ * GATES + n_ + 1]       = acc01 + b1v;
        C[(long)(m_ + 1) * GATES + n_ + 1] = acc11 + b1v;
    }
}

// ---------------------------------------------------------------------------
// Pa / Pb in one launch. grid (16,16,2), block 256.
// ---------------------------------------------------------------------------
__global__ void __launch_bounds__(256) pab_kernel(
    const float* __restrict__ H,
    const float* __restrict__ W1,
    const float* __restrict__ b1,
    float* __restrict__ P)
{
    const int z = blockIdx.z;
    const float* __restrict__ B = W1 + (z ? DHID : 0);
    float* __restrict__ C = P + (long)z * NN * MLPH;

    __shared__ float As[16][34];
    __shared__ float Bs[16][34];

    const int tid = threadIdx.x;
    const int ti = tid & 15;
    const int tn = tid >> 4;
    const int m0 = blockIdx.x * 32;
    const int n0 = blockIdx.y * 32;

    float acc00 = 0.f, acc01 = 0.f, acc10 = 0.f, acc11 = 0.f;

    for (int kc = 0; kc < DHID; kc += 16) {
#pragma unroll
        for (int it = 0; it < 2; ++it) {
            int idx = tid + it * 256;
            int mm = idx >> 4, kk = idx & 15;
            int k = kc + kk;
            As[kk][mm] = (k < DHID) ? H[(long)(m0 + mm) * DHID + k] : 0.f;
            Bs[kk][mm] = (k < DHID) ? B[(long)(n0 + mm) * 500 + k] : 0.f;
        }
        __syncthreads();
#pragma unroll
        for (int kk = 0; kk < 16; ++kk) {
            float2 av = *(const float2*)&As[kk][2 * ti];
            float2 bv = *(const float2*)&Bs[kk][2 * tn];
            acc00 = fmaf(av.x, bv.x, acc00);
            acc01 = fmaf(av.x, bv.y, acc01);
            acc10 = fmaf(av.y, bv.x, acc10);
            acc11 = fmaf(av.y, bv.y, acc11);
        }
        __syncthreads();
    }

    int m_ = m0 + 2 * ti;
    int n_ = n0 + 2 * tn;
    float b0 = 0.f, b1v = 0.f;
    if (z) { b0 = b1[n_]; b1v = b1[n_ + 1]; }
    C[(long)m_ * MLPH + n_]           = acc00 + b0;
    C[(long)m_ * MLPH + n_ + 1]       = acc01 + b1v;
    C[(long)(m_ + 1) * MLPH + n_]     = acc10 + b0;
    C[(long)(m_ + 1) * MLPH + n_ + 1] = acc11 + b1v;
}

// ---------------------------------------------------------------------------
// LSTM recurrence. grid = 2 (dir), block = 512.
// Thread r < 500 owns gate row r: cols 0..87 in packed-ull registers (44 ull),
// cols 88..123 as 9 float4 per row in smem, col 124 scalar in smem.
// Gate nonlinearities applied by each thread on its own row (parallel phase);
// the serial phase is just the c/h update on 125 threads.
// Smem layout (floats):
//   [0, 18000)      : float4 weights, [q in 0..8][row 0..499] (cols 88..123)
//   [18000, 18500)  : col-124 weights
//   [18500, 19012)  : activated gates (500 used)
//   [19012, 19140)  : h (125 used, padded to 128; offset 76048B, 16B aligned)
// ---------------------------------------------------------------------------
#define LSTM_SMEM_FLOATS (9 * 500 * 4 + 500 + 512 + 128)
#define LSTM_SMEM_BYTES  (LSTM_SMEM_FLOATS * 4)

__global__ void __launch_bounds__(512, 1) lstm_kernel(
    const float* __restrict__ Whh_f,
    const float* __restrict__ Whh_b,
    const float* __restrict__ A,     // [2][512][500]
    float* __restrict__ H)           // [512][250]
{
    extern __shared__ float smem[];
    float4* sh_w4  = (float4*)smem;              // 9*500 float4
    float*  sh_wl  = smem + 9 * 500 * 4;         // 500
    float*  sh_act = sh_wl + 500;                // 512
    float*  sh_h   = sh_act + 512;               // 128

    const int tid = threadIdx.x;
    const int dir = blockIdx.x;
    const float* __restrict__ Whh = dir ? Whh_b : Whh_f;
    const float* __restrict__ Ad = A + dir * (T_SEQ * GATES);
    const int r = tid;

    // stage smem weights: float4 for cols 88..123, scalar col 124
    for (int idx = tid; idx < 9 * 500; idx += 512) {
        int q = idx / 500, rr = idx - q * 500;
        const float* w = Whh + rr * 125 + 88 + 4 * q;
        sh_w4[q * 500 + rr] = make_float4(w[0], w[1], w[2], w[3]);
    }
    for (int idx = tid; idx < 500; idx += 512)
        sh_wl[idx] = Whh[idx * 125 + 124];

    // register weights: cols 0..87 packed as ull (2 fp32 each) -> 88 regs
    ull wreg[44];
    if (r < GATES) {
        const float* wf = Whh + r * 125;
#pragma unroll
        for (int p = 0; p < 44; ++p) {
            float2 t = make_float2(wf[2 * p], wf[2 * p + 1]);
            wreg[p] = *(ull*)&t;
        }
    }

    if (tid < 128) sh_h[tid] = 0.f;
    float creg = 0.f;
    float a_cur = (r < GATES) ? Ad[r] : 0.f;
    const bool is_g_gate = (r >= 250 && r < 375);
    __syncthreads();

    const ulonglong2* h2  = (const ulonglong2*)sh_h;
    const ulonglong2* w2p = (const ulonglong2*)sh_w4;

    for (int t = 0; t < T_SEQ; ++t) {
        float a_next = (r < GATES && t < T_SEQ - 1) ? Ad[(t + 1) * GATES + r] : 0.f;
        if (r < GATES) {
            ull acc_a = 0ull, acc_b = 0ull;
#pragma unroll
            for (int p = 0; p < 22; ++p) {     // cols 0..87 (registers)
                ulonglong2 hv = h2[p];
                acc_a = ffma2u(wreg[2 * p],     hv.x, acc_a);
                acc_b = ffma2u(wreg[2 * p + 1], hv.y, acc_b);
            }
#pragma unroll
            for (int q = 0; q < 9; ++q) {      // cols 88..123 (smem float4)
                ulonglong2 hv = h2[22 + q];
                ulonglong2 wv = w2p[q * 500 + r];
                acc_a = ffma2u(wv.x, hv.x, acc_a);
                acc_b = ffma2u(wv.y, hv.y, acc_b);
            }
            float2 fa = u2f2(acc_a);
            float2 fb = u2f2(acc_b);
            float s = fa.x + fa.y + fb.x + fb.y + sh_wl[r] * sh_h[124] + a_cur;
            // activate in the parallel phase: i,f,o -> sigmoid ; g -> tanh
            sh_act[r] = is_g_gate ? tanh_mufu(s) : sig_mufu(s);
        }
        __syncthreads();
        if (r < HID) {
            float iv = sh_act[r];
            float fv = sh_act[HID + r];
            float gv = sh_act[2 * HID + r];
            float ov = sh_act[3 * HID + r];
            creg = fv * creg + iv * gv;
            float hv = ov * tanh_mufu(creg);
            sh_h[r] = hv;
            int row = dir ? (T_SEQ - 1 - t) : t;
            H[row * DHID + dir * HID + r] = hv;
        }
        __syncthreads();
        a_cur = a_next;
    }
}

// ---------------------------------------------------------------------------
// Pairwise MLP contraction:
//   out[j][i] = b2 + sum_k W2[k] * tanh(Pa[i][k] + Pb[j][k])
// ---------------------------------------------------------------------------
__global__ void __launch_bounds__(256) pair_kernel(
    const float* __restrict__ Pa,   // [512][512]
    const float* __restrict__ Pb,   // [512][512] (b1 folded in)
    const float* __restrict__ W2,   // [512]
    const float* __restrict__ b2,   // [1]
    float* __restrict__ out)        // [512][512]  row=j, col=i
{
    __shared__ float pas[64][34];
    __shared__ float pbs[64][34];
    __shared__ float w2s[64];

    const int tid = threadIdx.x;
    const int ti = tid & 15;     // i pair
    const int tj = tid >> 4;     // j pair
    const int i0 = blockIdx.x * 32;
    const int j0 = blockIdx.y * 32;

    float acc00 = 0.f, acc01 = 0.f, acc10 = 0.f, acc11 = 0.f;

    for (int kc = 0; kc < MLPH; kc += 64) {
#pragma unroll
        for (int it = 0; it < 2; ++it) {
            int idx = tid + it * 256;
            int row = idx >> 4, q = idx & 15;
            float4 va = *(const float4*)&Pa[(long)(i0 + row) * MLPH + kc + 4 * q];
            pas[4 * q + 0][row] = va.x; pas[4 * q + 1][row] = va.y;
            pas[4 * q + 2][row] = va.z; pas[4 * q + 3][row] = va.w;
            float4 vb = *(const float4*)&Pb[(long)(j0 + row) * MLPH + kc + 4 * q];
            pbs[4 * q + 0][row] = vb.x; pbs[4 * q + 1][row] = vb.y;
            pbs[4 * q + 2][row] = vb.z; pbs[4 * q + 3][row] = vb.w;
        }
        if (tid < 16) {
            float4 w = *(const float4*)&W2[kc + 4 * tid];
            w2s[4 * tid + 0] = w.x; w2s[4 * tid + 1] = w.y;
            w2s[4 * tid + 2] = w.z; w2s[4 * tid + 3] = w.w;
        }
        __syncthreads();
#pragma unroll
        for (int kk = 0; kk < 64; ++kk) {
            float w = w2s[kk];
            float2 a = *(const float2*)&pas[kk][2 * ti];
            float2 b = *(const float2*)&pbs[kk][2 * tj];
            acc00 = fmaf(w, tanh_mufu(a.x + b.x), acc00);
            acc01 = fmaf(w, tanh_mufu(a.x + b.y), acc01);
            acc10 = fmaf(w, tanh_mufu(a.y + b.x), acc10);
            acc11 = fmaf(w, tanh_mufu(a.y + b.y), acc11);
        }
        __syncthreads();
    }

    float bb = b2[0];
    int i = i0 + 2 * ti;
    int j = j0 + 2 * tj;
    *(float2*)&out[(long)j * NN + i]       = make_float2(acc00 + bb, acc10 + bb);
    *(float2*)&out[(long)(j + 1) * NN + i] = make_float2(acc01 + bb, acc11 + bb);
}

// ---------------------------------------------------------------------------
// launch
// ---------------------------------------------------------------------------
extern "C" void kernel_launch(void* const* d_in, const int* in_sizes, int n_in,
                              void* d_out, int out_size)
{
    const float* x     = (const float*)d_in[0];   // (512,1,125)
    const float* Wih_f = (const float*)d_in[1];
    const float* Whh_f = (const float*)d_in[2];
    const float* bih_f = (const float*)d_in[3];
    const float* bhh_f = (const float*)d_in[4];
    const float* Wih_b = (const float*)d_in[5];
    const float* Whh_b = (const float*)d_in[6];
    const float* bih_b = (const float*)d_in[7];
    const float* bhh_b = (const float*)d_in[8];
    const float* W1    = (const float*)d_in[9];   // (512,500)
    const float* b1    = (const float*)d_in[10];  // (512)
    const float* W2    = (const float*)d_in[11];  // (1,512)
    const float* b2    = (const float*)d_in[12];  // (1)
    float* out = (float*)d_out;

    float *pA, *pH, *pP;
    cudaGetSymbolAddress((void**)&pA, g_A);
    cudaGetSymbolAddress((void**)&pH, g_H);
    cudaGetSymbolAddress((void**)&pP, g_P);
    float* pPa = pP;
    float* pPb = pP + NN * MLPH;

    cudaFuncSetAttribute(lstm_kernel,
                         cudaFuncAttributeMaxDynamicSharedMemorySize,
                         LSTM_SMEM_BYTES);

    dim3 blk(256);
    proj_kernel<<<dim3(16, 16, 2), blk>>>(x, Wih_f, bih_f, bhh_f,
                                          Wih_b, bih_b, bhh_b, pA);
    lstm_kernel<<<2, 512, LSTM_SMEM_BYTES>>>(Whh_f, Whh_b, pA, pH);
    pab_kernel<<<dim3(16, 16, 2), blk>>>(pH, W1, b1, pP);
    pair_kernel<<<dim3(16, 16), blk>>>(pPa, pPb, W2, b2, out);
}

// round 5
// speedup vs baseline: 1.0935x; 1.0935x over previous
#include <cuda_runtime.h>
#include <cuda_bf16.h>
#include <math.h>

#define T_SEQ   512
#define GATES   500
#define HID     125
#define DHID    250      // 2*HID
#define MLPH    512
#define NN      512

// Scratch (device globals; no allocation allowed)
__device__ float g_A[2 * T_SEQ * GATES];   // input projections (fwd/bwd)
__device__ float g_H[T_SEQ * DHID];        // concat hidden states
__device__ float g_P[2 * NN * MLPH];       // Pa, Pb(+b1)

// ---------------------------------------------------------------------------
// helpers
// ---------------------------------------------------------------------------
typedef unsigned long long ull;

__device__ __forceinline__ ull ffma2u(ull a, ull b, ull c) {
    ull d;
    asm("fma.rn.f32x2 %0, %1, %2, %3;" : "=l"(d) : "l"(a), "l"(b), "l"(c));
    return d;
}
__device__ __forceinline__ float2 u2f2(ull v) {
    float2 r;
    asm("mov.b64 {%0, %1}, %2;" : "=f"(r.x), "=f"(r.y) : "l"(v));
    return r;
}
// unpack packed bf16x2 (lo16 = even col, hi16 = odd col) to packed f32x2
__device__ __forceinline__ ull unpk(unsigned int v) {
    ull d;
    asm("{\n\t"
        ".reg .b32 lo, hi;\n\t"
        "shl.b32 lo, %1, 16;\n\t"
        "and.b32 hi, %1, 0xFFFF0000;\n\t"
        "mov.b64 %0, {lo, hi};\n\t"
        "}" : "=l"(d) : "r"(v));
    return d;
}
__device__ __forceinline__ float tanh_mufu(float x) {
    float y;
    asm("tanh.approx.f32 %0, %1;" : "=f"(y) : "f"(x));
    return y;
}
__device__ __forceinline__ float sig_mufu(float x) {
    return 0.5f * tanh_mufu(0.5f * x) + 0.5f;
}

// no-op kernels to shift the ncu capture slot onto lstm_kernel
__device__ int g_sink;
__global__ void nudge_kernel() {
    if (threadIdx.x > 4096) g_sink = 1;   // never taken
}

// ---------------------------------------------------------------------------
// Input projection, both directions in one launch.
// ---------------------------------------------------------------------------
__global__ void __launch_bounds__(256) proj_kernel(
    const float* __restrict__ x,
    const float* __restrict__ Wih_f, const float* __restrict__ bih_f,
    const float* __restrict__ bhh_f,
    const float* __restrict__ Wih_b, const float* __restrict__ bih_b,
    const float* __restrict__ bhh_b,
    float* __restrict__ Aout)
{
    const int dir = blockIdx.z;
    const float* __restrict__ W  = dir ? Wih_b : Wih_f;
    const float* __restrict__ bi = dir ? bih_b : bih_f;
    const float* __restrict__ bh = dir ? bhh_b : bhh_f;
    float* __restrict__ C = Aout + dir * (T_SEQ * GATES);

    __shared__ float As[16][34];
    __shared__ float Bs[16][34];

    const int tid = threadIdx.x;
    const int ti = tid & 15;
    const int tn = tid >> 4;
    const int m0 = blockIdx.x * 32;
    const int n0 = blockIdx.y * 32;

    float acc00 = 0.f, acc01 = 0.f, acc10 = 0.f, acc11 = 0.f;

    for (int kc = 0; kc < 125; kc += 16) {
#pragma unroll
        for (int it = 0; it < 2; ++it) {
            int idx = tid + it * 256;
            int mm = idx >> 4, kk = idx & 15;
            int k = kc + kk;
            int m = m0 + mm;
            int ra = dir ? (T_SEQ - 1 - m) : m;
            As[kk][mm] = (k < 125) ? x[(long)ra * 125 + k] : 0.f;
            int n = n0 + mm;
            Bs[kk][mm] = (n < GATES && k < 125) ? W[(long)n * 125 + k] : 0.f;
        }
        __syncthreads();
#pragma unroll
        for (int kk = 0; kk < 16; ++kk) {
            float2 av = *(const float2*)&As[kk][2 * ti];
            float2 bv = *(const float2*)&Bs[kk][2 * tn];
            acc00 = fmaf(av.x, bv.x, acc00);
            acc01 = fmaf(av.x, bv.y, acc01);
            acc10 = fmaf(av.y, bv.x, acc10);
            acc11 = fmaf(av.y, bv.y, acc11);
        }
        __syncthreads();
    }

    int m_ = m0 + 2 * ti;
    int n_ = n0 + 2 * tn;
    float b0 = 0.f, b1v = 0.f;
    if (n_ < GATES)     b0  = bi[n_] + bh[n_];
    if (n_ + 1 < GATES) b1v = bi[n_ + 1] + bh[n_ + 1];
    if (n_ < GATES) {
        C[(long)m_ * GATES + n_]       = acc00 + b0;
        C[(long)(m_ + 1) * GATES + n_] = acc10 + b0;
    }
    if (n_ + 1 < GATES) {
        C[(long)m_ * GATES + n_ + 1]       = acc01 + b1v;
        C[(long)(m_ + 1) * GATES + n_ + 1] = acc11 + b1v;
    }
}

// ---------------------------------------------------------------------------
// Pa / Pb in one launch. grid (16,16,2), block 256.
// ---------------------------------------------------------------------------
__global__ void __launch_bounds__(256) pab_kernel(
    const float* __restrict__ H,
    const float* __restrict__ W1,
    const float* __restrict__ b1,
    float* __restrict__ P)
{
    const int z = blockIdx.z;
    const float* __restrict__ B = W1 + (z ? DHID : 0);
    float* __restrict__ C = P + (long)z * NN * MLPH;

    __shared__ float As[16][34];
    __shared__ float Bs[16][34];

    const int tid = threadIdx.x;
    const int ti = tid & 15;
    const int tn = tid >> 4;
    const int m0 = blockIdx.x * 32;
    const int n0 = blockIdx.y * 32;

    float acc00 = 0.f, acc01 = 0.f, acc10 = 0.f, acc11 = 0.f;

    for (int kc = 0; kc < DHID; kc += 16) {
#pragma unroll
        for (int it = 0; it < 2; ++it) {
            int idx = tid + it * 256;
            int mm = idx >> 4, kk = idx & 15;
            int k = kc + kk;
            As[kk][mm] = (k < DHID) ? H[(long)(m0 + mm) * DHID + k] : 0.f;
            Bs[kk][mm] = (k < DHID) ? B[(long)(n0 + mm) * 500 + k] : 0.f;
        }
        __syncthreads();
#pragma unroll
        for (int kk = 0; kk < 16; ++kk) {
            float2 av = *(const float2*)&As[kk][2 * ti];
            float2 bv = *(const float2*)&Bs[kk][2 * tn];
            acc00 = fmaf(av.x, bv.x, acc00);
            acc01 = fmaf(av.x, bv.y, acc01);
            acc10 = fmaf(av.y, bv.x, acc10);
            acc11 = fmaf(av.y, bv.y, acc11);
        }
        __syncthreads();
    }

    int m_ = m0 + 2 * ti;
    int n_ = n0 + 2 * tn;
    float b0 = 0.f, b1v = 0.f;
    if (z) { b0 = b1[n_]; b1v = b1[n_ + 1]; }
    C[(long)m_ * MLPH + n_]           = acc00 + b0;
    C[(long)m_ * MLPH + n_ + 1]       = acc01 + b1v;
    C[(long)(m_ + 1) * MLPH + n_]     = acc10 + b0;
    C[(long)(m_ + 1) * MLPH + n_ + 1] = acc11 + b1v;
}

// ---------------------------------------------------------------------------
// LSTM recurrence. grid = 2 (dir), block = 512.
// Thread r < 500 owns gate row r:
//   cols 0..87   : fp32 in registers, packed ull (44 regs*2)
//   cols 88..127 : bf16x2 in smem (5 x uint4 per row; cols 125..127 = 0)
// h padded to 128 floats (h[125..127] = 0 always).
// Gate nonlinearities in the parallel phase; serial phase = c/h update only.
// ---------------------------------------------------------------------------
__global__ void __launch_bounds__(512, 1) lstm_kernel(
    const float* __restrict__ Whh_f,
    const float* __restrict__ Whh_b,
    const float* __restrict__ A,     // [2][512][500]
    float* __restrict__ H)           // [512][250]
{
    __shared__ __align__(16) uint4 sh_wb[5 * 500];   // bf16 weights, 40KB
    __shared__ __align__(16) float sh_act[512];
    __shared__ __align__(16) float sh_h[128];

    const int tid = threadIdx.x;
    const int dir = blockIdx.x;
    const float* __restrict__ Whh = dir ? Whh_b : Whh_f;
    const float* __restrict__ Ad = A + dir * (T_SEQ * GATES);
    const int r = tid;

    // stage bf16 smem weights: cols 88..127 (>=125 zero)
    for (int idx = tid; idx < 5 * 500; idx += 512) {
        int q = idx / 500, rr = idx - q * 500;
        const float* w = Whh + rr * 125;
        unsigned int u[4];
#pragma unroll
        for (int j = 0; j < 4; ++j) {
            int c0 = 88 + 8 * q + 2 * j;
            int c1 = c0 + 1;
            unsigned short b0 = (c0 < 125) ?
                __bfloat16_as_ushort(__float2bfloat16_rn(w[c0])) : 0;
            unsigned short b1 = (c1 < 125) ?
                __bfloat16_as_ushort(__float2bfloat16_rn(w[c1])) : 0;
            u[j] = ((unsigned int)b1 << 16) | b0;
        }
        sh_wb[q * 500 + rr] = make_uint4(u[0], u[1], u[2], u[3]);
    }

    // register weights: cols 0..87 packed as ull (2 fp32 each) -> 88 regs
    ull wreg[44];
    if (r < GATES) {
        const float* wf = Whh + r * 125;
#pragma unroll
        for (int p = 0; p < 44; ++p) {
            float2 t = make_float2(wf[2 * p], wf[2 * p + 1]);
            wreg[p] = *(ull*)&t;
        }
    }

    if (tid < 128) sh_h[tid] = 0.f;        // includes the 3 pad slots
    float creg = 0.f;
    float a_cur = (r < GATES) ? Ad[r] : 0.f;
    const bool is_g_gate = (r >= 250 && r < 375);
    __syncthreads();

    const ulonglong2* h2 = (const ulonglong2*)sh_h;   // 32 granules of 16B

    for (int t = 0; t < T_SEQ; ++t) {
        float a_next = (r < GATES && t < T_SEQ - 1) ? Ad[(t + 1) * GATES + r] : 0.f;
        if (r < GATES) {
            ull acc_a = 0ull, acc_b = 0ull;
#pragma unroll
            for (int p = 0; p < 22; ++p) {     // cols 0..87 (registers)
                ulonglong2 hv = h2[p];
                acc_a = ffma2u(wreg[2 * p],     hv.x, acc_a);
                acc_b = ffma2u(wreg[2 * p + 1], hv.y, acc_b);
            }
#pragma unroll
            for (int q = 0; q < 5; ++q) {      // cols 88..127 (bf16 smem)
                uint4 wq = sh_wb[q * 500 + r];
                ulonglong2 hA = h2[22 + 2 * q];
                ulonglong2 hB = h2[23 + 2 * q];
                acc_a = ffma2u(unpk(wq.x), hA.x, acc_a);
                acc_b = ffma2u(unpk(wq.y), hA.y, acc_b);
                acc_a = ffma2u(unpk(wq.z), hB.x, acc_a);
                acc_b = ffma2u(unpk(wq.w), hB.y, acc_b);
            }
            float2 fa = u2f2(acc_a);
            float2 fb = u2f2(acc_b);
            float s = fa.x + fa.y + fb.x + fb.y + a_cur;
            sh_act[r] = is_g_gate ? tanh_mufu(s) : sig_mufu(s);
        }
        __syncthreads();
        if (r < HID) {
            float iv = sh_act[r];
            float fv = sh_act[HID + r];
            float gv = sh_act[2 * HID + r];
            float ov = sh_act[3 * HID + r];
            creg = fv * creg + iv * gv;
            float hv = ov * tanh_mufu(creg);
            sh_h[r] = hv;
            int row = dir ? (T_SEQ - 1 - t) : t;
            H[row * DHID + dir * HID + r] = hv;
        }
        __syncthreads();
        a_cur = a_next;
    }
}

// ---------------------------------------------------------------------------
// Pairwise MLP contraction:
//   out[j][i] = b2 + sum_k W2[k] * tanh(Pa[i][k] + Pb[j][k])
// ---------------------------------------------------------------------------
__global__ void __launch_bounds__(256) pair_kernel(
    const float* __restrict__ Pa,   // [512][512]
    const float* __restrict__ Pb,   // [512][512] (b1 folded in)
    const float* __restrict__ W2,   // [512]
    const float* __restrict__ b2,   // [1]
    float* __restrict__ out)        // [512][512]  row=j, col=i
{
    __shared__ float pas[64][34];
    __shared__ float pbs[64][34];
    __shared__ float w2s[64];

    const int tid = threadIdx.x;
    const int ti = tid & 15;     // i pair
    const int tj = tid >> 4;     // j pair
    const int i0 = blockIdx.x * 32;
    const int j0 = blockIdx.y * 32;

    float acc00 = 0.f, acc01 = 0.f, acc10 = 0.f, acc11 = 0.f;

    for (int kc = 0; kc < MLPH; kc += 64) {
#pragma unroll
        for (int it = 0; it < 2; ++it) {
            int idx = tid + it * 256;
            int row = idx >> 4, q = idx & 15;
            float4 va = *(const float4*)&Pa[(long)(i0 + row) * MLPH + kc + 4 * q];
            pas[4 * q + 0][row] = va.x; pas[4 * q + 1][row] = va.y;
            pas[4 * q + 2][row] = va.z; pas[4 * q + 3][row] = va.w;
            float4 vb = *(const float4*)&Pb[(long)(j0 + row) * MLPH + kc + 4 * q];
            pbs[4 * q + 0][row] = vb.x; pbs[4 * q + 1][row] = vb.y;
            pbs[4 * q + 2][row] = vb.z; pbs[4 * q + 3][row] = vb.w;
        }
        if (tid < 16) {
            float4 w = *(const float4*)&W2[kc + 4 * tid];
            w2s[4 * tid + 0] = w.x; w2s[4 * tid + 1] = w.y;
            w2s[4 * tid + 2] = w.z; w2s[4 * tid + 3] = w.w;
        }
        __syncthreads();
#pragma unroll
        for (int kk = 0; kk < 64; ++kk) {
            float w = w2s[kk];
            float2 a = *(const float2*)&pas[kk][2 * ti];
            float2 b = *(const float2*)&pbs[kk][2 * tj];
            acc00 = fmaf(w, tanh_mufu(a.x + b.x), acc00);
            acc01 = fmaf(w, tanh_mufu(a.x + b.y), acc01);
            acc10 = fmaf(w, tanh_mufu(a.y + b.x), acc10);
            acc11 = fmaf(w, tanh_mufu(a.y + b.y), acc11);
        }
        __syncthreads();
    }

    float bb = b2[0];
    int i = i0 + 2 * ti;
    int j = j0 + 2 * tj;
    *(float2*)&out[(long)j * NN + i]       = make_float2(acc00 + bb, acc10 + bb);
    *(float2*)&out[(long)(j + 1) * NN + i] = make_float2(acc01 + bb, acc11 + bb);
}

// ---------------------------------------------------------------------------
// launch
// ---------------------------------------------------------------------------
extern "C" void kernel_launch(void* const* d_in, const int* in_sizes, int n_in,
                              void* d_out, int out_size)
{
    const float* x     = (const float*)d_in[0];   // (512,1,125)
    const float* Wih_f = (const float*)d_in[1];
    const float* Whh_f = (const float*)d_in[2];
    const float* bih_f = (const float*)d_in[3];
    const float* bhh_f = (const float*)d_in[4];
    const float* Wih_b = (const float*)d_in[5];
    const float* Whh_b = (const float*)d_in[6];
    const float* bih_b = (const float*)d_in[7];
    const float* bhh_b = (const float*)d_in[8];
    const float* W1    = (const float*)d_in[9];   // (512,500)
    const float* b1    = (const float*)d_in[10];  // (512)
    const float* W2    = (const float*)d_in[11];  // (1,512)
    const float* b2    = (const float*)d_in[12];  // (1)
    float* out = (float*)d_out;

    float *pA, *pH, *pP;
    cudaGetSymbolAddress((void**)&pA, g_A);
    cudaGetSymbolAddress((void**)&pH, g_H);
    cudaGetSymbolAddress((void**)&pP, g_P);
    float* pPa = pP;
    float* pPb = pP + NN * MLPH;

    dim3 blk(256);
    // slot-shift so ncu's captured launch lands on lstm_kernel
    nudge_kernel<<<1, 32>>>();
    nudge_kernel<<<1, 32>>>();
    proj_kernel<<<dim3(16, 16, 2), blk>>>(x, Wih_f, bih_f, bhh_f,
                                          Wih_b, bih_b, bhh_b, pA);
    lstm_kernel<<<2, 512>>>(Whh_f, Whh_b, pA, pH);
    pab_kernel<<<dim3(16, 16, 2), blk>>>(pH, W1, b1, pP);
    pair_kernel<<<dim3(16, 16), blk>>>(pPa, pPb, W2, b2, out);
}

// round 6
// speedup vs baseline: 1.3789x; 1.2609x over previous
#include <cuda_runtime.h>
#include <cuda_bf16.h>
#include <math.h>

#define T_SEQ   512
#define GATES   500
#define HID     125
#define DHID    250      // 2*HID
#define MLPH    512
#define NN      512

// Scratch (device globals; no allocation allowed)
__device__ float g_A[2 * T_SEQ * GATES];   // input projections (fwd/bwd)
__device__ float g_H[T_SEQ * DHID];        // concat hidden states
__device__ float g_P[2 * NN * MLPH];       // Pa, Pb(+b1)

// ---------------------------------------------------------------------------
// helpers
// ---------------------------------------------------------------------------
typedef unsigned long long ull;

__device__ __forceinline__ ull ffma2u(ull a, ull b, ull c) {
    ull d;
    asm("fma.rn.f32x2 %0, %1, %2, %3;" : "=l"(d) : "l"(a), "l"(b), "l"(c));
    return d;
}
__device__ __forceinline__ float2 u2f2(ull v) {
    float2 r;
    asm("mov.b64 {%0, %1}, %2;" : "=f"(r.x), "=f"(r.y) : "l"(v));
    return r;
}
// unpack packed bf16x2 (lo16 = even col, hi16 = odd col) to packed f32x2
__device__ __forceinline__ ull unpk(unsigned int v) {
    ull d;
    asm("{\n\t"
        ".reg .b32 lo, hi;\n\t"
        "shl.b32 lo, %1, 16;\n\t"
        "and.b32 hi, %1, 0xFFFF0000;\n\t"
        "mov.b64 %0, {lo, hi};\n\t"
        "}" : "=l"(d) : "r"(v));
    return d;
}
__device__ __forceinline__ float tanh_mufu(float x) {
    float y;
    asm("tanh.approx.f32 %0, %1;" : "=f"(y) : "f"(x));
    return y;
}
__device__ __forceinline__ float sig_mufu(float x) {
    return 0.5f * tanh_mufu(0.5f * x) + 0.5f;
}

// no-op kernels to keep the ncu capture slot on lstm_kernel
__device__ int g_sink;
__global__ void nudge_kernel() {
    if (threadIdx.x > 4096) g_sink = 1;   // never taken
}

// ---------------------------------------------------------------------------
// Input projection, both directions in one launch.
// ---------------------------------------------------------------------------
__global__ void __launch_bounds__(256) proj_kernel(
    const float* __restrict__ x,
    const float* __restrict__ Wih_f, const float* __restrict__ bih_f,
    const float* __restrict__ bhh_f,
    const float* __restrict__ Wih_b, const float* __restrict__ bih_b,
    const float* __restrict__ bhh_b,
    float* __restrict__ Aout)
{
    const int dir = blockIdx.z;
    const float* __restrict__ W  = dir ? Wih_b : Wih_f;
    const float* __restrict__ bi = dir ? bih_b : bih_f;
    const float* __restrict__ bh = dir ? bhh_b : bhh_f;
    float* __restrict__ C = Aout + dir * (T_SEQ * GATES);

    __shared__ float As[16][34];
    __shared__ float Bs[16][34];

    const int tid = threadIdx.x;
    const int ti = tid & 15;
    const int tn = tid >> 4;
    const int m0 = blockIdx.x * 32;
    const int n0 = blockIdx.y * 32;

    float acc00 = 0.f, acc01 = 0.f, acc10 = 0.f, acc11 = 0.f;

    for (int kc = 0; kc < 125; kc += 16) {
#pragma unroll
        for (int it = 0; it < 2; ++it) {
            int idx = tid + it * 256;
            int mm = idx >> 4, kk = idx & 15;
            int k = kc + kk;
            int m = m0 + mm;
            int ra = dir ? (T_SEQ - 1 - m) : m;
            As[kk][mm] = (k < 125) ? x[(long)ra * 125 + k] : 0.f;
            int n = n0 + mm;
            Bs[kk][mm] = (n < GATES && k < 125) ? W[(long)n * 125 + k] : 0.f;
        }
        __syncthreads();
#pragma unroll
        for (int kk = 0; kk < 16; ++kk) {
            float2 av = *(const float2*)&As[kk][2 * ti];
            float2 bv = *(const float2*)&Bs[kk][2 * tn];
            acc00 = fmaf(av.x, bv.x, acc00);
            acc01 = fmaf(av.x, bv.y, acc01);
            acc10 = fmaf(av.y, bv.x, acc10);
            acc11 = fmaf(av.y, bv.y, acc11);
        }
        __syncthreads();
    }

    int m_ = m0 + 2 * ti;
    int n_ = n0 + 2 * tn;
    float b0 = 0.f, b1v = 0.f;
    if (n_ < GATES)     b0  = bi[n_] + bh[n_];
    if (n_ + 1 < GATES) b1v = bi[n_ + 1] + bh[n_ + 1];
    if (n_ < GATES) {
        C[(long)m_ * GATES + n_]       = acc00 + b0;
        C[(long)(m_ + 1) * GATES + n_] = acc10 + b0;
    }
    if (n_ + 1 < GATES) {
        C[(long)m_ * GATES + n_ + 1]       = acc01 + b1v;
        C[(long)(m_ + 1) * GATES + n_ + 1] = acc11 + b1v;
    }
}

// ---------------------------------------------------------------------------
// Pa / Pb in one launch. grid (16,16,2), block 256.
// ---------------------------------------------------------------------------
__global__ void __launch_bounds__(256) pab_kernel(
    const float* __restrict__ H,
    const float* __restrict__ W1,
    const float* __restrict__ b1,
    float* __restrict__ P)
{
    const int z = blockIdx.z;
    const float* __restrict__ B = W1 + (z ? DHID : 0);
    float* __restrict__ C = P + (long)z * NN * MLPH;

    __shared__ float As[16][34];
    __shared__ float Bs[16][34];

    const int tid = threadIdx.x;
    const int ti = tid & 15;
    const int tn = tid >> 4;
    const int m0 = blockIdx.x * 32;
    const int n0 = blockIdx.y * 32;

    float acc00 = 0.f, acc01 = 0.f, acc10 = 0.f, acc11 = 0.f;

    for (int kc = 0; kc < DHID; kc += 16) {
#pragma unroll
        for (int it = 0; it < 2; ++it) {
            int idx = tid + it * 256;
            int mm = idx >> 4, kk = idx & 15;
            int k = kc + kk;
            As[kk][mm] = (k < DHID) ? H[(long)(m0 + mm) * DHID + k] : 0.f;
            Bs[kk][mm] = (k < DHID) ? B[(long)(n0 + mm) * 500 + k] : 0.f;
        }
        __syncthreads();
#pragma unroll
        for (int kk = 0; kk < 16; ++kk) {
            float2 av = *(const float2*)&As[kk][2 * ti];
            float2 bv = *(const float2*)&Bs[kk][2 * tn];
            acc00 = fmaf(av.x, bv.x, acc00);
            acc01 = fmaf(av.x, bv.y, acc01);
            acc10 = fmaf(av.y, bv.x, acc10);
            acc11 = fmaf(av.y, bv.y, acc11);
        }
        __syncthreads();
    }

    int m_ = m0 + 2 * ti;
    int n_ = n0 + 2 * tn;
    float b0 = 0.f, b1v = 0.f;
    if (z) { b0 = b1[n_]; b1v = b1[n_ + 1]; }
    C[(long)m_ * MLPH + n_]           = acc00 + b0;
    C[(long)m_ * MLPH + n_ + 1]       = acc01 + b1v;
    C[(long)(m_ + 1) * MLPH + n_]     = acc10 + b0;
    C[(long)(m_ + 1) * MLPH + n_ + 1] = acc11 + b1v;
}

// ---------------------------------------------------------------------------
// LSTM recurrence, 2 rows per thread. grid = 2 (dir), block = 256.
// Thread t: u = t & 127 (active u < 125), half = t >> 7.
//   half 0 -> rows rA = u       (i-gate),  rB = 250 + u (g-gate)
//   half 1 -> rows rA = 125 + u (f-gate),  rB = 375 + u (o-gate)
// Each thread loads h ONCE per step and uses it for both rows.
// Weights: cols 0..87 of both rows in registers (88 ull = 88 regs... pairs),
//          cols 88..127 bf16x2 in smem (5 uint4 per row; cols >=125 zero).
// Update: half0 writes i*g to smem; half1 owns c: c = f*c + ig; h = o*tanh(c).
// ---------------------------------------------------------------------------
__global__ void __launch_bounds__(256, 1) lstm_kernel(
    const float* __restrict__ Whh_f,
    const float* __restrict__ Whh_b,
    const float* __restrict__ A,     // [2][512][500]
    float* __restrict__ H)           // [512][250]
{
    __shared__ __align__(16) uint4 sh_wb[5 * 500];   // bf16 weights, 40KB
    __shared__ __align__(16) float sh_ig[128];       // i*g products
    __shared__ __align__(16) float sh_h[128];        // h (125 used, pad 0)

    const int tid = threadIdx.x;
    const int dir = blockIdx.x;
    const float* __restrict__ Whh = dir ? Whh_b : Whh_f;
    const float* __restrict__ Ad = A + dir * (T_SEQ * GATES);

    const int u    = tid & 127;
    const int half = tid >> 7;
    const bool act = (u < HID);
    const int rA = half * 125 + u;          // i or f row
    const int rB = 250 + half * 125 + u;    // g or o row

    // stage bf16 smem weights: cols 88..127 (>=125 zero), layout [q][row]
    for (int idx = tid; idx < 5 * 500; idx += 256) {
        int q = idx / 500, rr = idx - q * 500;
        const float* w = Whh + rr * 125;
        unsigned int uu[4];
#pragma unroll
        for (int j = 0; j < 4; ++j) {
            int c0 = 88 + 8 * q + 2 * j;
            int c1 = c0 + 1;
            unsigned short b0 = (c0 < 125) ?
                __bfloat16_as_ushort(__float2bfloat16_rn(w[c0])) : 0;
            unsigned short b1 = (c1 < 125) ?
                __bfloat16_as_ushort(__float2bfloat16_rn(w[c1])) : 0;
            uu[j] = ((unsigned int)b1 << 16) | b0;
        }
        sh_wb[q * 500 + rr] = make_uint4(uu[0], uu[1], uu[2], uu[3]);
    }

    // register weights: cols 0..87 of both rows, packed ull
    ull wA[44], wB[44];
    if (act) {
        const float* fA = Whh + rA * 125;
        const float* fB = Whh + rB * 125;
#pragma unroll
        for (int p = 0; p < 44; ++p) {
            float2 tA = make_float2(fA[2 * p], fA[2 * p + 1]);
            float2 tB = make_float2(fB[2 * p], fB[2 * p + 1]);
            wA[p] = *(ull*)&tA;
            wB[p] = *(ull*)&tB;
        }
    }

    if (tid < 128) sh_h[tid] = 0.f;   // includes pad slots
    float creg = 0.f;
    float aA = act ? Ad[rA] : 0.f;
    float aB = act ? Ad[rB] : 0.f;
    __syncthreads();

    const ulonglong2* h2 = (const ulonglong2*)sh_h;   // 32 granules of 16B

    for (int t = 0; t < T_SEQ; ++t) {
        const bool has_next = (t < T_SEQ - 1);
        float aA_n = (act && has_next) ? Ad[(t + 1) * GATES + rA] : 0.f;
        float aB_n = (act && has_next) ? Ad[(t + 1) * GATES + rB] : 0.f;

        float fo_f = 0.f, fo_o = 0.f;   // half1's f and o
        if (act) {
            ull accA0 = 0ull, accA1 = 0ull, accB0 = 0ull, accB1 = 0ull;
#pragma unroll
            for (int p = 0; p < 22; ++p) {     // cols 0..87 (registers)
                ulonglong2 hv = h2[p];
                accA0 = ffma2u(wA[2 * p],     hv.x, accA0);
                accA1 = ffma2u(wA[2 * p + 1], hv.y, accA1);
                accB0 = ffma2u(wB[2 * p],     hv.x, accB0);
                accB1 = ffma2u(wB[2 * p + 1], hv.y, accB1);
            }
#pragma unroll
            for (int q = 0; q < 5; ++q) {      // cols 88..127 (bf16 smem)
                ulonglong2 hA = h2[22 + 2 * q];
                ulonglong2 hB = h2[23 + 2 * q];
                uint4 wqA = sh_wb[q * 500 + rA];
                uint4 wqB = sh_wb[q * 500 + rB];
                accA0 = ffma2u(unpk(wqA.x), hA.x, accA0);
                accA1 = ffma2u(unpk(wqA.y), hA.y, accA1);
                accA0 = ffma2u(unpk(wqA.z), hB.x, accA0);
                accA1 = ffma2u(unpk(wqA.w), hB.y, accA1);
                accB0 = ffma2u(unpk(wqB.x), hA.x, accB0);
                accB1 = ffma2u(unpk(wqB.y), hA.y, accB1);
                accB0 = ffma2u(unpk(wqB.z), hB.x, accB0);
                accB1 = ffma2u(unpk(wqB.w), hB.y, accB1);
            }
            float2 a0 = u2f2(accA0), a1 = u2f2(accA1);
            float2 b0 = u2f2(accB0), b1 = u2f2(accB1);
            float sA = a0.x + a0.y + a1.x + a1.y + aA;
            float sB = b0.x + b0.y + b1.x + b1.y + aB;
            float actA = sig_mufu(sA);                       // i or f
            float actB = half ? sig_mufu(sB) : tanh_mufu(sB); // o or g
            if (half == 0) {
                sh_ig[u] = actA * actB;    // i*g
            } else {
                fo_f = actA; fo_o = actB;
            }
        }
        __syncthreads();
        if (act && half == 1) {
            creg = fo_f * creg + sh_ig[u];
            float hv = fo_o * tanh_mufu(creg);
            sh_h[u] = hv;
            int row = dir ? (T_SEQ - 1 - t) : t;
            H[row * DHID + dir * HID + u] = hv;
        }
        __syncthreads();
        aA = aA_n; aB = aB_n;
    }
}

// ---------------------------------------------------------------------------
// Pairwise MLP contraction:
//   out[j][i] = b2 + sum_k W2[k] * tanh(Pa[i][k] + Pb[j][k])
// ---------------------------------------------------------------------------
__global__ void __launch_bounds__(256) pair_kernel(
    const float* __restrict__ Pa,   // [512][512]
    const float* __restrict__ Pb,   // [512][512] (b1 folded in)
    const float* __restrict__ W2,   // [512]
    const float* __restrict__ b2,   // [1]
    float* __restrict__ out)        // [512][512]  row=j, col=i
{
    __shared__ float pas[64][34];
    __shared__ float pbs[64][34];
    __shared__ float w2s[64];

    const int tid = threadIdx.x;
    const int ti = tid & 15;     // i pair
    const int tj = tid >> 4;     // j pair
    const int i0 = blockIdx.x * 32;
    const int j0 = blockIdx.y * 32;

    float acc00 = 0.f, acc01 = 0.f, acc10 = 0.f, acc11 = 0.f;

    for (int kc = 0; kc < MLPH; kc += 64) {
#pragma unroll
        for (int it = 0; it < 2; ++it) {
            int idx = tid + it * 256;
            int row = idx >> 4, q = idx & 15;
            float4 va = *(const float4*)&Pa[(long)(i0 + row) * MLPH + kc + 4 * q];
            pas[4 * q + 0][row] = va.x; pas[4 * q + 1][row] = va.y;
            pas[4 * q + 2][row] = va.z; pas[4 * q + 3][row] = va.w;
            float4 vb = *(const float4*)&Pb[(long)(j0 + row) * MLPH + kc + 4 * q];
            pbs[4 * q + 0][row] = vb.x; pbs[4 * q + 1][row] = vb.y;
            pbs[4 * q + 2][row] = vb.z; pbs[4 * q + 3][row] = vb.w;
        }
        if (tid < 16) {
            float4 w = *(const float4*)&W2[kc + 4 * tid];
            w2s[4 * tid + 0] = w.x; w2s[4 * tid + 1] = w.y;
            w2s[4 * tid + 2] = w.z; w2s[4 * tid + 3] = w.w;
        }
        __syncthreads();
#pragma unroll
        for (int kk = 0; kk < 64; ++kk) {
            float w = w2s[kk];
            float2 a = *(const float2*)&pas[kk][2 * ti];
            float2 b = *(const float2*)&pbs[kk][2 * tj];
            acc00 = fmaf(w, tanh_mufu(a.x + b.x), acc00);
            acc01 = fmaf(w, tanh_mufu(a.x + b.y), acc01);
            acc10 = fmaf(w, tanh_mufu(a.y + b.x), acc10);
            acc11 = fmaf(w, tanh_mufu(a.y + b.y), acc11);
        }
        __syncthreads();
    }

    float bb = b2[0];
    int i = i0 + 2 * ti;
    int j = j0 + 2 * tj;
    *(float2*)&out[(long)j * NN + i]       = make_float2(acc00 + bb, acc10 + bb);
    *(float2*)&out[(long)(j + 1) * NN + i] = make_float2(acc01 + bb, acc11 + bb);
}

// ---------------------------------------------------------------------------
// launch
// ---------------------------------------------------------------------------
extern "C" void kernel_launch(void* const* d_in, const int* in_sizes, int n_in,
                              void* d_out, int out_size)
{
    const float* x     = (const float*)d_in[0];   // (512,1,125)
    const float* Wih_f = (const float*)d_in[1];
    const float* Whh_f = (const float*)d_in[2];
    const float* bih_f = (const float*)d_in[3];
    const float* bhh_f = (const float*)d_in[4];
    const float* Wih_b = (const float*)d_in[5];
    const float* Whh_b = (const float*)d_in[6];
    const float* bih_b = (const float*)d_in[7];
    const float* bhh_b = (const float*)d_in[8];
    const float* W1    = (const float*)d_in[9];   // (512,500)
    const float* b1    = (const float*)d_in[10];  // (512)
    const float* W2    = (const float*)d_in[11];  // (1,512)
    const float* b2    = (const float*)d_in[12];  // (1)
    float* out = (float*)d_out;

    float *pA, *pH, *pP;
    cudaGetSymbolAddress((void**)&pA, g_A);
    cudaGetSymbolAddress((void**)&pH, g_H);
    cudaGetSymbolAddress((void**)&pP, g_P);
    float* pPa = pP;
    float* pPb = pP + NN * MLPH;

    dim3 blk(256);
    // keep launch-slot layout so ncu's captured launch stays on lstm_kernel
    nudge_kernel<<<1, 32>>>();
    nudge_kernel<<<1, 32>>>();
    proj_kernel<<<dim3(16, 16, 2), blk>>>(x, Wih_f, bih_f, bhh_f,
                                          Wih_b, bih_b, bhh_b, pA);
    lstm_kernel<<<2, 256>>>(Whh_f, Whh_b, pA, pH);
    pab_kernel<<<dim3(16, 16, 2), blk>>>(pH, W1, b1, pP);
    pair_kernel<<<dim3(16, 16), blk>>>(pPa, pPb, W2, b2, out);
}